// round 11
// baseline (speedup 1.0000x reference)
#include <cuda_runtime.h>
#include <math.h>

#define NT    512
#define NBLK  592
#define BATCH 50000
#define BT    4
#define NQUAD (BATCH / BT)

// ---- shared memory layout (float offsets) ----
#define O_ISF 0        // ISFT fp32 [p=96][k, stride 52], zero pads (p>=90, k>=45)
#define O_SFT 4992     // SFTT fp32 [k=48][p, stride 100], zero pads
#define O_SC  9792     // scale[45] (pad 48)
#define O_A   9840     // x / gemm2-out buffer [256 rows][46]   row = ch*4+bi
#define O_T   21616    // sconv out fp32 [256 rows][52], cols 45..51 zero
#define O_SIG 34928    // sig [128 rows][100]
#define SMEM_FLOATS 47728
#define SMEM_BYTES  (SMEM_FLOATS * 4)

#define SA 46
#define ST 52
#define SS 100

// ---- tf32 truncation split: 2 fixed-lat ops, no cvt chains ----
__device__ __forceinline__ void split_tf32(float x, unsigned &hi, unsigned &lo) {
    unsigned xb = __float_as_uint(x);
    hi = xb & 0xFFFFE000u;
    lo = __float_as_uint(x - __uint_as_float(hi));
}
__device__ __forceinline__ void mma8(float d[4], const unsigned a[4], const unsigned b[2]) {
    asm volatile(
        "mma.sync.aligned.m16n8k8.row.col.f32.tf32.tf32.f32 "
        "{%0,%1,%2,%3}, {%4,%5,%6,%7}, {%8,%9}, {%0,%1,%2,%3};"
        : "+f"(d[0]), "+f"(d[1]), "+f"(d[2]), "+f"(d[3])
        : "r"(a[0]), "r"(a[1]), "r"(a[2]), "r"(a[3]), "r"(b[0]), "r"(b[1]));
}

// sconv k-tiles aligned to degree-group boundaries (single ls_idx per tile)
__constant__ int c_tk0[15] = {0, 1, 5, 6, 10, 14, 15, 19, 23, 27, 28, 32, 36, 40, 44};
__constant__ int c_tkl[15] = {1, 4, 1, 4, 4, 1, 4, 4, 4, 1, 4, 4, 4, 4, 1};
__constant__ int c_td[15]  = {0, 1, 1, 2, 2, 2, 3, 3, 3, 3, 4, 4, 4, 4, 4};

// sconv: T[och*4+bi][k] = scale[k] * sum_c A[c*4+bi][k] * W[och][c][d(k)]
// single-phase: reads A, writes fp32 T (separate buffer, no race).
template <int Cin, int Cout, int OT>
__device__ __forceinline__ void sconv_step(float* sm, const float* __restrict__ gw, int tid)
{
    constexpr int SLOTS = BT * (Cout / OT) * 15;
    if (tid < SLOTS) {
        const int kt = tid % 15;
        const int bi = (tid / 15) & 3;
        const int ot = tid / (15 * BT);
        const int k0   = c_tk0[kt];
        const int klen = c_tkl[kt];
        const int d    = c_td[kt];
        const float* __restrict__ A = sm + O_A + bi * SA + k0;
        const float* __restrict__ W = gw + (ot * OT) * (Cin * 5) + d;

        float acc[OT][4];
#pragma unroll
        for (int i = 0; i < OT; i++)
#pragma unroll
            for (int j = 0; j < 4; j++) acc[i][j] = 0.f;

#pragma unroll 4
        for (int c = 0; c < Cin; c++) {
            float xv[4];
#pragma unroll
            for (int j = 0; j < 4; j++) xv[j] = A[c * (4 * SA) + j];
#pragma unroll
            for (int i = 0; i < OT; i++) {
                float w = __ldg(W + i * (Cin * 5) + c * 5);
#pragma unroll
                for (int j = 0; j < 4; j++) acc[i][j] = fmaf(w, xv[j], acc[i][j]);
            }
        }

        float* __restrict__ Tp = sm + O_T + ((ot * OT) * 4 + bi) * ST + k0;
#pragma unroll
        for (int i = 0; i < OT; i++)
#pragma unroll
            for (int j = 0; j < 4; j++)
                if (j < klen) Tp[i * (4 * ST) + j] = acc[i][j] * sm[O_SC + k0 + j];
    }
}

// GEMM1 (MMA): sig[m][p] = relu( sum_k T[trow0+m][k]*ISF[k][p] ), K=48, N=96
// fp32 loads for A and B, mask-split in registers (half the crossbar bytes).
template <int MT, int MW>
__device__ __forceinline__ void gemm1_mma(float* sm, int trow0, int w, int lane)
{
    const int mw = w & 3, nw = w >> 2;
    if (mw < MW) {
        const int g = lane >> 2, t = lane & 3;
        float d[MT][3][4];
#pragma unroll
        for (int i = 0; i < MT; i++)
#pragma unroll
            for (int nt = 0; nt < 3; nt++)
#pragma unroll
                for (int r = 0; r < 4; r++) d[i][nt][r] = 0.f;

        const float* Tb = sm + O_T + trow0 * ST;
#pragma unroll
        for (int kc = 0; kc < 6; kc++) {
            const int k0 = kc * 8;
            unsigned ahi[MT][4], alo[MT][4];
#pragma unroll
            for (int i = 0; i < MT; i++) {
                const int m0 = (mw * MT + i) * 16;
                float a0 = Tb[(m0 + g) * ST + k0 + t];       // T cols 45..51 zero
                float a1 = Tb[(m0 + g + 8) * ST + k0 + t];
                float a2 = Tb[(m0 + g) * ST + k0 + t + 4];
                float a3 = Tb[(m0 + g + 8) * ST + k0 + t + 4];
                split_tf32(a0, ahi[i][0], alo[i][0]);
                split_tf32(a1, ahi[i][1], alo[i][1]);
                split_tf32(a2, ahi[i][2], alo[i][2]);
                split_tf32(a3, ahi[i][3], alo[i][3]);
            }
#pragma unroll
            for (int nt = 0; nt < 3; nt++) {
                const int n0 = nw * 24 + nt * 8;
                float b0 = sm[O_ISF + (n0 + g) * ST + k0 + t];
                float b1 = sm[O_ISF + (n0 + g) * ST + k0 + t + 4];
                unsigned bh[2], bl[2];
                split_tf32(b0, bh[0], bl[0]);
                split_tf32(b1, bh[1], bl[1]);
#pragma unroll
                for (int i = 0; i < MT; i++) {
                    mma8(d[i][nt], ahi[i], bh);
                    mma8(d[i][nt], ahi[i], bl);
                    mma8(d[i][nt], alo[i], bh);
                }
            }
        }
#pragma unroll
        for (int i = 0; i < MT; i++) {
            const int m0 = (mw * MT + i) * 16;
#pragma unroll
            for (int nt = 0; nt < 3; nt++) {
                const int n0 = nw * 24 + nt * 8;
                float2 v0 = make_float2(fmaxf(d[i][nt][0], 0.f), fmaxf(d[i][nt][1], 0.f));
                float2 v1 = make_float2(fmaxf(d[i][nt][2], 0.f), fmaxf(d[i][nt][3], 0.f));
                *reinterpret_cast<float2*>(sm + O_SIG + (m0 + g) * SS + n0 + 2 * t) = v0;
                *reinterpret_cast<float2*>(sm + O_SIG + (m0 + g + 8) * SS + n0 + 2 * t) = v1;
            }
        }
    }
}

// GEMM2 (MMA): A[arow0+m][k] = sum_p sig[m][p] * SFT[p][k], K=96, N=48
// fp32 loads for A (sig) and B (SFT), mask-split in registers.
template <int MW2>
__device__ __forceinline__ void gemm2_mma(float* sm, int arow0, int w, int lane)
{
    const int mw = w >> 1, nw = w & 1;
    if (mw < MW2) {
        const int g = lane >> 2, t = lane & 3;
        const int m0 = mw * 16;
        float d[3][4];
#pragma unroll
        for (int nt = 0; nt < 3; nt++)
#pragma unroll
            for (int r = 0; r < 4; r++) d[nt][r] = 0.f;

#pragma unroll
        for (int pc = 0; pc < 12; pc++) {
            const int p0 = pc * 8;
            unsigned ahi[4], alo[4];
            float a0 = sm[O_SIG + (m0 + g) * SS + p0 + t];
            float a1 = sm[O_SIG + (m0 + g + 8) * SS + p0 + t];
            float a2 = sm[O_SIG + (m0 + g) * SS + p0 + t + 4];
            float a3 = sm[O_SIG + (m0 + g + 8) * SS + p0 + t + 4];
            split_tf32(a0, ahi[0], alo[0]);
            split_tf32(a1, ahi[1], alo[1]);
            split_tf32(a2, ahi[2], alo[2]);
            split_tf32(a3, ahi[3], alo[3]);
#pragma unroll
            for (int nt = 0; nt < 3; nt++) {
                const int n0 = nw * 24 + nt * 8;
                float b0 = sm[O_SFT + (n0 + g) * SS + p0 + t];
                float b1 = sm[O_SFT + (n0 + g) * SS + p0 + t + 4];
                unsigned bh[2], bl[2];
                split_tf32(b0, bh[0], bl[0]);
                split_tf32(b1, bh[1], bl[1]);
                mma8(d[nt], ahi, bh);
                mma8(d[nt], ahi, bl);
                mma8(d[nt], alo, bh);
            }
        }
#pragma unroll
        for (int nt = 0; nt < 3; nt++) {
            const int n0 = nw * 24 + nt * 8;
            const int col = n0 + 2 * t;
            if (col < 46) {
                *reinterpret_cast<float2*>(sm + O_A + (arow0 + m0 + g) * SA + col) =
                    make_float2(d[nt][0], d[nt][1]);
                *reinterpret_cast<float2*>(sm + O_A + (arow0 + m0 + g + 8) * SA + col) =
                    make_float2(d[nt][2], d[nt][3]);
            }
        }
    }
}

template <int Cin, int Cout, int OT>
__device__ __forceinline__ void run_layer(float* sm, const float* __restrict__ gw, int tid)
{
    sconv_step<Cin, Cout, OT>(sm, gw, tid);
    __syncthreads();
    const int w = tid >> 5, lane = tid & 31;
    constexpr int NCHB = (Cout + 31) / 32;
    constexpr int M = 4 * (Cout < 32 ? Cout : 32);
#pragma unroll
    for (int cb = 0; cb < NCHB; cb++) {
        if constexpr (M == 128)      gemm1_mma<2, 4>(sm, cb * 128, w, lane);
        else if constexpr (M == 64)  gemm1_mma<1, 4>(sm, 0, w, lane);
        else                         gemm1_mma<1, 1>(sm, 0, w, lane);
        __syncthreads();
        if constexpr (M == 128)      gemm2_mma<8>(sm, cb * 128, w, lane);
        else if constexpr (M == 64)  gemm2_mma<4>(sm, 0, w, lane);
        else                         gemm2_mma<1>(sm, 0, w, lane);
        __syncthreads();
    }
}

extern "C" __global__ void __launch_bounds__(NT, 1)
scnn_kernel(const float* __restrict__ x, const float* __restrict__ sft,
            const float* __restrict__ isft,
            const float* __restrict__ w1, const float* __restrict__ w2,
            const float* __restrict__ w3, const float* __restrict__ w4,
            const float* __restrict__ w5, const float* __restrict__ w6,
            float* __restrict__ out)
{
    extern __shared__ float sm[];
    const int tid = threadIdx.x;

    // ---- stage ISFT fp32: [p][k], stride 52, zero pads ----
    for (int i = tid; i < 96 * ST; i += NT) {
        int p = i / ST, k = i - p * ST;
        sm[O_ISF + i] = (p < 90 && k < 45) ? isft[p * 45 + k] : 0.f;
    }
    // ---- stage SFTT fp32: [k][p], stride 100, zero pads ----
    for (int i = tid; i < 48 * SS; i += NT) {
        int k = i / SS, p = i - k * SS;
        sm[O_SFT + i] = (k < 45 && p < 90) ? sft[k * 90 + p] : 0.f;
    }
    if (tid < 45) {
        int k = tid;
        int dd = (k >= 28) ? 4 : (k >= 15) ? 3 : (k >= 6) ? 2 : (k >= 1) ? 1 : 0;
        sm[O_SC + k] = sqrtf(3.14159265358979323846f / (float)(4 * dd + 1));
    }
    // ---- zero T pad cols 45..51 (sconv never writes them) ----
    for (int i = tid; i < 256 * 7; i += NT) {
        int r = i / 7, c = 45 + (i - (i / 7) * 7);
        sm[O_T + r * ST + c] = 0.f;
    }
    __syncthreads();

    // ---- persistent stride loop over batch quads ----
    for (int quad = blockIdx.x; quad < NQUAD; quad += gridDim.x) {
        const int b0 = quad * BT;

        // load x: rows c*4+bi, cols 0..44
        for (int i = tid; i < BT * 4 * 45; i += NT) {
            int bi = i / 180, r = i - bi * 180;
            int c = r / 45, k = r - c * 45;
            sm[O_A + (c * 4 + bi) * SA + k] = x[(b0 + bi) * 180 + r];
        }
        __syncthreads();

        run_layer<4,  16, 2>(sm, w1, tid);
        run_layer<16, 32, 4>(sm, w2, tid);
        run_layer<32, 64, 8>(sm, w3, tid);
        run_layer<64, 32, 4>(sm, w4, tid);
        run_layer<32, 16, 2>(sm, w5, tid);
        run_layer<16, 4,  1>(sm, w6, tid);

        // store output
        for (int i = tid; i < BT * 180; i += NT) {
            int bi = i / 180, r = i - bi * 180;
            int c = r / 45, k = r - c * 45;
            out[(b0 + bi) * 180 + r] = sm[O_A + (c * 4 + bi) * SA + k];
        }
        __syncthreads();   // protect A before next iteration's load
    }
}

extern "C" void kernel_launch(void* const* d_in, const int* in_sizes, int n_in,
                              void* d_out, int out_size)
{
    cudaFuncSetAttribute(scnn_kernel, cudaFuncAttributeMaxDynamicSharedMemorySize,
                         SMEM_BYTES);
    scnn_kernel<<<NBLK, NT, SMEM_BYTES>>>(
        (const float*)d_in[0], (const float*)d_in[1], (const float*)d_in[2],
        (const float*)d_in[3], (const float*)d_in[4], (const float*)d_in[5],
        (const float*)d_in[6], (const float*)d_in[7], (const float*)d_in[8],
        (float*)d_out);
}

// round 12
// speedup vs baseline: 1.0591x; 1.0591x over previous
#include <cuda_runtime.h>
#include <math.h>

#define NT    256
#define NBLK  1184
#define BATCH 50000
#define BT    2
#define NPAIR (BATCH / BT)

// ---- shared memory layout (float offsets), 22896 floats = 91.6 KB/CTA ----
#define O_ISF 0        // ISFT fp32 [p=96][k, stride 52], zero pads (p>=90, k>=45)
#define O_SFT 4992     // SFTT fp32 [k=48][p, stride 100], zero pads (k>=45, p>=90)
#define O_SC  9792     // scale[45] (pad 48)
#define O_AT  9840     // unified x / T / gemm2-out buffer [128 rows][52], row = ch*2+bi
#define O_SIG 16496    // sig [64 rows][100]
#define SMEM_FLOATS 22896
#define SMEM_BYTES  (SMEM_FLOATS * 4)

#define ST 52
#define SS 100

// ---- tf32 truncation split: 2 fixed-lat ops ----
__device__ __forceinline__ void split_tf32(float x, unsigned &hi, unsigned &lo) {
    unsigned xb = __float_as_uint(x);
    hi = xb & 0xFFFFE000u;
    lo = __float_as_uint(x - __uint_as_float(hi));
}
__device__ __forceinline__ void mma8(float d[4], const unsigned a[4], const unsigned b[2]) {
    asm volatile(
        "mma.sync.aligned.m16n8k8.row.col.f32.tf32.tf32.f32 "
        "{%0,%1,%2,%3}, {%4,%5,%6,%7}, {%8,%9}, {%0,%1,%2,%3};"
        : "+f"(d[0]), "+f"(d[1]), "+f"(d[2]), "+f"(d[3])
        : "r"(a[0]), "r"(a[1]), "r"(a[2]), "r"(a[3]), "r"(b[0]), "r"(b[1]));
}

// sconv k-tiles aligned to degree-group boundaries (single ls_idx per tile)
__constant__ int c_tk0[15] = {0, 1, 5, 6, 10, 14, 15, 19, 23, 27, 28, 32, 36, 40, 44};
__constant__ int c_tkl[15] = {1, 4, 1, 4, 4, 1, 4, 4, 4, 1, 4, 4, 4, 4, 1};
__constant__ int c_td[15]  = {0, 1, 1, 2, 2, 2, 3, 3, 3, 3, 4, 4, 4, 4, 4};

// sconv (two-phase, in-place in AT): read A rows c*2+bi -> regs, barrier,
// write T rows och*2+bi (cols 0..44; 45..47 hold zeros from prior gemm2/init).
template <int Cin, int Cout, int OT>
__device__ __forceinline__ void sconv_step(float* sm, const float* __restrict__ gw, int tid)
{
    constexpr int SLOTS = BT * (Cout / OT) * 15;
    const int kt = tid % 15;
    const int bi = (tid / 15) & 1;
    const int ot = tid / (15 * BT);
    const int k0   = c_tk0[kt];
    const int klen = c_tkl[kt];
    const int d    = c_td[kt];

    float acc[OT][4];
#pragma unroll
    for (int i = 0; i < OT; i++)
#pragma unroll
        for (int j = 0; j < 4; j++) acc[i][j] = 0.f;

    if (tid < SLOTS) {
        const float* __restrict__ A = sm + O_AT + bi * ST + k0;
        const float* __restrict__ W = gw + (ot * OT) * (Cin * 5) + d;
#pragma unroll 4
        for (int c = 0; c < Cin; c++) {
            float xv[4];
#pragma unroll
            for (int j = 0; j < 4; j++) xv[j] = A[c * (2 * ST) + j];
#pragma unroll
            for (int i = 0; i < OT; i++) {
                float w = __ldg(W + i * (Cin * 5) + c * 5);
#pragma unroll
                for (int j = 0; j < 4; j++) acc[i][j] = fmaf(w, xv[j], acc[i][j]);
            }
        }
    }
    __syncthreads();   // all A reads done before T overwrites the same buffer

    if (tid < SLOTS) {
        float* __restrict__ Tp = sm + O_AT + ((ot * OT) * 2 + bi) * ST + k0;
#pragma unroll
        for (int i = 0; i < OT; i++)
#pragma unroll
            for (int j = 0; j < 4; j++)
                if (j < klen) Tp[i * (2 * ST) + j] = acc[i][j] * sm[O_SC + k0 + j];
    }
}

// GEMM1 (MMA): sig[m][p] = relu( sum_k T[trow0+m][k]*ISF[k][p] ), K=48, N=96
// 8 warps: mw = w&1 (MT m16-tiles each), nw = w>>1 (4 n-groups of 24).
template <int MT, int MW>
__device__ __forceinline__ void gemm1_mma(float* sm, int trow0, int w, int lane)
{
    const int mw = w & 1, nw = w >> 1;
    if (mw < MW) {
        const int g = lane >> 2, t = lane & 3;
        float d[MT][3][4];
#pragma unroll
        for (int i = 0; i < MT; i++)
#pragma unroll
            for (int nt = 0; nt < 3; nt++)
#pragma unroll
                for (int r = 0; r < 4; r++) d[i][nt][r] = 0.f;

        const float* Tb = sm + O_AT + trow0 * ST;
#pragma unroll
        for (int kc = 0; kc < 6; kc++) {
            const int k0 = kc * 8;
            unsigned ahi[MT][4], alo[MT][4];
#pragma unroll
            for (int i = 0; i < MT; i++) {
                const int m0 = (mw * MT + i) * 16;
                float a0 = Tb[(m0 + g) * ST + k0 + t];
                float a1 = Tb[(m0 + g + 8) * ST + k0 + t];
                float a2 = Tb[(m0 + g) * ST + k0 + t + 4];
                float a3 = Tb[(m0 + g + 8) * ST + k0 + t + 4];
                split_tf32(a0, ahi[i][0], alo[i][0]);
                split_tf32(a1, ahi[i][1], alo[i][1]);
                split_tf32(a2, ahi[i][2], alo[i][2]);
                split_tf32(a3, ahi[i][3], alo[i][3]);
            }
#pragma unroll
            for (int nt = 0; nt < 3; nt++) {
                const int n0 = nw * 24 + nt * 8;
                float b0 = sm[O_ISF + (n0 + g) * ST + k0 + t];
                float b1 = sm[O_ISF + (n0 + g) * ST + k0 + t + 4];
                unsigned bh[2], bl[2];
                split_tf32(b0, bh[0], bl[0]);
                split_tf32(b1, bh[1], bl[1]);
#pragma unroll
                for (int i = 0; i < MT; i++) {
                    mma8(d[i][nt], ahi[i], bh);
                    mma8(d[i][nt], ahi[i], bl);
                    mma8(d[i][nt], alo[i], bh);
                }
            }
        }
#pragma unroll
        for (int i = 0; i < MT; i++) {
            const int m0 = (mw * MT + i) * 16;
#pragma unroll
            for (int nt = 0; nt < 3; nt++) {
                const int n0 = nw * 24 + nt * 8;
                float2 v0 = make_float2(fmaxf(d[i][nt][0], 0.f), fmaxf(d[i][nt][1], 0.f));
                float2 v1 = make_float2(fmaxf(d[i][nt][2], 0.f), fmaxf(d[i][nt][3], 0.f));
                *reinterpret_cast<float2*>(sm + O_SIG + (m0 + g) * SS + n0 + 2 * t) = v0;
                *reinterpret_cast<float2*>(sm + O_SIG + (m0 + g + 8) * SS + n0 + 2 * t) = v1;
            }
        }
    }
}

// GEMM2 (MMA): AT[arow0+m][k] = sum_p sig[m][p] * SFT[p][k], K=96, N=48
// 8 warps: mw = w>>1 (1 m16-tile each), nw = w&1 (2 n-groups of 24).
// Stores cols 0..47: cols 45..47 get zeros (SFT rows 45..47 zero) -> maintains pad.
// FULL=0 (M=8 case): skip +8-row stores (rows 8..15 are garbage lanes).
template <int MTILES, int FULL>
__device__ __forceinline__ void gemm2_mma(float* sm, int arow0, int w, int lane)
{
    const int mw = w >> 1, nw = w & 1;
    if (mw < MTILES) {
        const int g = lane >> 2, t = lane & 3;
        const int m0 = mw * 16;
        float d[3][4];
#pragma unroll
        for (int nt = 0; nt < 3; nt++)
#pragma unroll
            for (int r = 0; r < 4; r++) d[nt][r] = 0.f;

#pragma unroll
        for (int pc = 0; pc < 12; pc++) {
            const int p0 = pc * 8;
            unsigned ahi[4], alo[4];
            float a0 = sm[O_SIG + (m0 + g) * SS + p0 + t];
            float a1 = sm[O_SIG + (m0 + g + 8) * SS + p0 + t];
            float a2 = sm[O_SIG + (m0 + g) * SS + p0 + t + 4];
            float a3 = sm[O_SIG + (m0 + g + 8) * SS + p0 + t + 4];
            split_tf32(a0, ahi[0], alo[0]);
            split_tf32(a1, ahi[1], alo[1]);
            split_tf32(a2, ahi[2], alo[2]);
            split_tf32(a3, ahi[3], alo[3]);
#pragma unroll
            for (int nt = 0; nt < 3; nt++) {
                const int n0 = nw * 24 + nt * 8;
                float b0 = sm[O_SFT + (n0 + g) * SS + p0 + t];
                float b1 = sm[O_SFT + (n0 + g) * SS + p0 + t + 4];
                unsigned bh[2], bl[2];
                split_tf32(b0, bh[0], bl[0]);
                split_tf32(b1, bh[1], bl[1]);
                mma8(d[nt], ahi, bh);
                mma8(d[nt], ahi, bl);
                mma8(d[nt], alo, bh);
            }
        }
#pragma unroll
        for (int nt = 0; nt < 3; nt++) {
            const int n0 = nw * 24 + nt * 8;
            const int col = n0 + 2 * t;     // <= 46, col+1 <= 47 < ST
            *reinterpret_cast<float2*>(sm + O_AT + (arow0 + m0 + g) * ST + col) =
                make_float2(d[nt][0], d[nt][1]);
            if (FULL)
                *reinterpret_cast<float2*>(sm + O_AT + (arow0 + m0 + g + 8) * ST + col) =
                    make_float2(d[nt][2], d[nt][3]);
        }
    }
}

template <int Cin, int Cout, int OT>
__device__ __forceinline__ void run_layer(float* sm, const float* __restrict__ gw, int tid)
{
    sconv_step<Cin, Cout, OT>(sm, gw, tid);   // internal barrier
    __syncthreads();
    const int w = tid >> 5, lane = tid & 31;
    constexpr int NCHB = (Cout + 31) / 32;
    constexpr int M = BT * (Cout < 32 ? Cout : 32);
#pragma unroll
    for (int cb = 0; cb < NCHB; cb++) {
        if constexpr (M == 64)       gemm1_mma<2, 2>(sm, cb * 64, w, lane);
        else if constexpr (M == 32)  gemm1_mma<1, 2>(sm, 0, w, lane);
        else                         gemm1_mma<1, 1>(sm, 0, w, lane);
        __syncthreads();
        if constexpr (M == 64)       gemm2_mma<4, 1>(sm, cb * 64, w, lane);
        else if constexpr (M == 32)  gemm2_mma<2, 1>(sm, 0, w, lane);
        else                         gemm2_mma<1, 0>(sm, 0, w, lane);
        __syncthreads();
    }
}

extern "C" __global__ void __launch_bounds__(NT, 2)
scnn_kernel(const float* __restrict__ x, const float* __restrict__ sft,
            const float* __restrict__ isft,
            const float* __restrict__ w1, const float* __restrict__ w2,
            const float* __restrict__ w3, const float* __restrict__ w4,
            const float* __restrict__ w5, const float* __restrict__ w6,
            float* __restrict__ out)
{
    extern __shared__ float sm[];
    const int tid = threadIdx.x;

    // ---- stage ISFT fp32 [p][k] stride 52, zero pads ----
    for (int i = tid; i < 96 * ST; i += NT) {
        int p = i / ST, k = i - p * ST;
        sm[O_ISF + i] = (p < 90 && k < 45) ? isft[p * 45 + k] : 0.f;
    }
    // ---- stage SFTT fp32 [k][p] stride 100, zero pads ----
    for (int i = tid; i < 48 * SS; i += NT) {
        int k = i / SS, p = i - k * SS;
        sm[O_SFT + i] = (k < 45 && p < 90) ? sft[k * 90 + p] : 0.f;
    }
    if (tid < 45) {
        int k = tid;
        int dd = (k >= 28) ? 4 : (k >= 15) ? 3 : (k >= 6) ? 2 : (k >= 1) ? 1 : 0;
        sm[O_SC + k] = sqrtf(3.14159265358979323846f / (float)(4 * dd + 1));
    }
    // ---- zero AT pad cols 45..51 for all 128 rows (first-quad invariant) ----
    for (int i = tid; i < 128 * 7; i += NT) {
        int r = i / 7, c = 45 + (i - (i / 7) * 7);
        sm[O_AT + r * ST + c] = 0.f;
    }
    __syncthreads();

    // ---- persistent stride loop over batch pairs ----
    for (int pair = blockIdx.x; pair < NPAIR; pair += gridDim.x) {
        const int b0 = pair * BT;

        // load x: rows c*2+bi, cols 0..44
        for (int i = tid; i < BT * 180; i += NT) {
            int bi = i / 180, r = i - bi * 180;
            int c = r / 45, k = r - c * 45;
            sm[O_AT + (c * 2 + bi) * ST + k] = x[(b0 + bi) * 180 + r];
        }
        __syncthreads();

        run_layer<4,  16, 2>(sm, w1, tid);
        run_layer<16, 32, 4>(sm, w2, tid);
        run_layer<32, 64, 8>(sm, w3, tid);
        run_layer<64, 32, 4>(sm, w4, tid);
        run_layer<32, 16, 2>(sm, w5, tid);
        run_layer<16, 4,  1>(sm, w6, tid);

        // store output: rows c*2+bi
        for (int i = tid; i < BT * 180; i += NT) {
            int bi = i / 180, r = i - bi * 180;
            int c = r / 45, k = r - c * 45;
            out[(b0 + bi) * 180 + r] = sm[O_AT + (c * 2 + bi) * ST + k];
        }
        __syncthreads();   // protect AT before next iteration's load
    }
}

extern "C" void kernel_launch(void* const* d_in, const int* in_sizes, int n_in,
                              void* d_out, int out_size)
{
    cudaFuncSetAttribute(scnn_kernel, cudaFuncAttributeMaxDynamicSharedMemorySize,
                         SMEM_BYTES);
    scnn_kernel<<<NBLK, NT, SMEM_BYTES>>>(
        (const float*)d_in[0], (const float*)d_in[1], (const float*)d_in[2],
        (const float*)d_in[3], (const float*)d_in[4], (const float*)d_in[5],
        (const float*)d_in[6], (const float*)d_in[7], (const float*)d_in[8],
        (float*)d_out);
}